// round 7
// baseline (speedup 1.0000x reference)
#include <cuda_runtime.h>
#include <math.h>

#define NN 100000
#define EE 3200000
#define IN_F 256
#define ATT_D 128
#define SLOPE 0.2f

// ---------------- device scratch (no runtime allocation allowed) ----------
__device__ float g_wsrc[IN_F];
__device__ float g_wdst[IN_F];
__device__ float g_ssrc[NN];
__device__ float g_sdst[NN];
__device__ float g_denom[NN];
__device__ float g_rden[NN];
__device__ int   g_srcix[EE];   // int32 src staged by edgeB for edgeC
__device__ int   g_is64;        // 1 if edge buffer is int64, 0 if int32

// ---------------- fused pre-pass -------------------------------------------
__global__ void k_pre(const float* __restrict__ W, const float* __restrict__ a,
                      const long long* __restrict__ edge, int n, int B0) {
    int b = blockIdx.x;
    if (b < B0) {
        int i = b * blockDim.x + threadIdx.x;
        if (i < n) g_denom[i] = 0.0f;
    } else if (b == B0) {
        __shared__ float sa[2 * ATT_D];
        int t = threadIdx.x;            // 256 threads
        sa[t] = a[t];
        __syncthreads();
        const float* row = W + (size_t)t * ATT_D;
        float ws = 0.f, wd = 0.f;
#pragma unroll 8
        for (int j = 0; j < ATT_D; ++j) {
            float w = row[j];
            ws += w * sa[j];
            wd += w * sa[ATT_D + j];
        }
        g_wsrc[t] = ws;
        g_wdst[t] = wd;
    } else {
        // dtype sniff: int32 data read as int64 goes out of [0,n) with prob ~1
        if (threadIdx.x == 0) {
            int is64 = 1;
            for (int i = 0; i < 256; ++i) {
                long long v = edge[i];
                if (v < 0 || v >= (long long)n) { is64 = 0; break; }
            }
            g_is64 = is64;
        }
    }
}

// ---------------- node scores: 2 rows per warp for MLP ----------------------
__global__ void k_node_scores(const float* __restrict__ x, int n) {
    int gw   = (blockIdx.x * blockDim.x + threadIdx.x) >> 5;  // warp id
    int lane = threadIdx.x & 31;
    int r0 = gw * 2, r1 = r0 + 1;
    if (r0 >= n) return;
    bool has1 = (r1 < n);
    const float4* x0 = reinterpret_cast<const float4*>(x + (size_t)r0 * IN_F);
    const float4* x1 = reinterpret_cast<const float4*>(x + (size_t)(has1 ? r1 : r0) * IN_F);
    const float4* ws = reinterpret_cast<const float4*>(g_wsrc);
    const float4* wd = reinterpret_cast<const float4*>(g_wdst);
    float a00 = 0.f, a01 = 0.f, a10 = 0.f, a11 = 0.f;
#pragma unroll
    for (int k = 0; k < IN_F / 4 / 32; ++k) {   // 2 iters
        float4 v0 = x0[lane + 32 * k];
        float4 v1 = x1[lane + 32 * k];
        float4 sv = __ldg(&ws[lane + 32 * k]);
        float4 dv = __ldg(&wd[lane + 32 * k]);
        a00 += v0.x * sv.x + v0.y * sv.y + v0.z * sv.z + v0.w * sv.w;
        a01 += v0.x * dv.x + v0.y * dv.y + v0.z * dv.z + v0.w * dv.w;
        a10 += v1.x * sv.x + v1.y * sv.y + v1.z * sv.z + v1.w * sv.w;
        a11 += v1.x * dv.x + v1.y * dv.y + v1.z * dv.z + v1.w * dv.w;
    }
#pragma unroll
    for (int off = 16; off; off >>= 1) {
        a00 += __shfl_xor_sync(0xffffffffu, a00, off);
        a01 += __shfl_xor_sync(0xffffffffu, a01, off);
        a10 += __shfl_xor_sync(0xffffffffu, a10, off);
        a11 += __shfl_xor_sync(0xffffffffu, a11, off);
    }
    if (lane == 0) {
        g_ssrc[r0] = a00;
        g_sdst[r0] = a01;
        if (has1) { g_ssrc[r1] = a10; g_sdst[r1] = a11; }
    }
}

// ---------------- edge pass 1: ex = exp(leaky(score)); segment-sum ----------
// 8 edges/thread. MUFU(EX2)-bound; memory traffic (incl. srcix staging for
// edgeC) hides under the MUFU floor. No max subtraction: scores analytically
// bounded (|s| < ~30 << 88).
__global__ void k_edgeB(const void* __restrict__ edge_raw,
                        float* __restrict__ out, int e_cnt, int n) {
    int i = (blockIdx.x * blockDim.x + threadIdx.x) << 3;
    if (i >= e_cnt) return;
    const unsigned nm1 = (unsigned)(n - 1);
    int src[8], dst[8];
    bool full = (i + 7 < e_cnt);
    if (g_is64) {
        const long long* ep = (const long long*)edge_raw;
        if (full) {
#pragma unroll
            for (int q = 0; q < 4; ++q) {
                longlong2 s = *(const longlong2*)(ep + i + 2 * q);
                longlong2 d = *(const longlong2*)(ep + (size_t)e_cnt + i + 2 * q);
                src[2 * q] = (int)s.x; src[2 * q + 1] = (int)s.y;
                dst[2 * q] = (int)d.x; dst[2 * q + 1] = (int)d.y;
            }
        } else {
            for (int k = 0; k < 8; ++k) {
                int e = min(i + k, e_cnt - 1);
                src[k] = (int)ep[e];
                dst[k] = (int)ep[(size_t)e_cnt + e];
            }
        }
    } else {
        const int* ep = (const int*)edge_raw;
        if (full) {
#pragma unroll
            for (int q = 0; q < 2; ++q) {
                int4 s = *(const int4*)(ep + i + 4 * q);
                int4 d = *(const int4*)(ep + (size_t)e_cnt + i + 4 * q);
                src[4 * q] = s.x; src[4 * q + 1] = s.y; src[4 * q + 2] = s.z; src[4 * q + 3] = s.w;
                dst[4 * q] = d.x; dst[4 * q + 1] = d.y; dst[4 * q + 2] = d.z; dst[4 * q + 3] = d.w;
            }
        } else {
            for (int k = 0; k < 8; ++k) {
                int e = min(i + k, e_cnt - 1);
                src[k] = ep[e];
                dst[k] = ep[(size_t)e_cnt + e];
            }
        }
    }
    float ex[8];
#pragma unroll
    for (int k = 0; k < 8; ++k) {
        unsigned ss = min((unsigned)src[k], nm1);
        unsigned dd = min((unsigned)dst[k], nm1);
        src[k] = (int)ss;
        float s = g_ssrc[ss] + g_sdst[dd];
        s = (s >= 0.f) ? s : SLOPE * s;
        ex[k] = __expf(s);
    }
    if (full) {
        *reinterpret_cast<float4*>(out + i)     = make_float4(ex[0], ex[1], ex[2], ex[3]);
        *reinterpret_cast<float4*>(out + i + 4) = make_float4(ex[4], ex[5], ex[6], ex[7]);
        *reinterpret_cast<int4*>(g_srcix + i)     = make_int4(src[0], src[1], src[2], src[3]);
        *reinterpret_cast<int4*>(g_srcix + i + 4) = make_int4(src[4], src[5], src[6], src[7]);
#pragma unroll
        for (int k = 0; k < 8; ++k) atomicAdd(&g_denom[src[k]], ex[k]);
    } else {
        for (int k = 0; k < 8 && i + k < e_cnt; ++k) {
            out[i + k]      = ex[k];
            g_srcix[i + k]  = src[k];
            atomicAdd(&g_denom[src[k]], ex[k]);
        }
    }
}

// ---------------- reciprocal pass (moves 3.2M divides off the edge path) ----
__global__ void k_recip(int n) {
    int i = blockIdx.x * blockDim.x + threadIdx.x;
    if (i < n) g_rden[i] = 1.0f / (g_denom[i] + 1e-16f);
}

// ---------------- edge pass 2: pure multiply stream -------------------------
__global__ void k_edgeC(float* __restrict__ out, int e_cnt) {
    int i = (blockIdx.x * blockDim.x + threadIdx.x) << 3;
    if (i >= e_cnt) return;
    if (i + 7 < e_cnt) {
        int4 s0 = *reinterpret_cast<const int4*>(g_srcix + i);
        int4 s1 = *reinterpret_cast<const int4*>(g_srcix + i + 4);
        float4 v0 = *reinterpret_cast<const float4*>(out + i);
        float4 v1 = *reinterpret_cast<const float4*>(out + i + 4);
        v0.x *= g_rden[s0.x]; v0.y *= g_rden[s0.y];
        v0.z *= g_rden[s0.z]; v0.w *= g_rden[s0.w];
        v1.x *= g_rden[s1.x]; v1.y *= g_rden[s1.y];
        v1.z *= g_rden[s1.z]; v1.w *= g_rden[s1.w];
        *reinterpret_cast<float4*>(out + i)     = v0;
        *reinterpret_cast<float4*>(out + i + 4) = v1;
    } else {
        for (int k = 0; k < 8 && i + k < e_cnt; ++k)
            out[i + k] *= g_rden[g_srcix[i + k]];
    }
}

// ---------------- launch ------------------------------------------------------
extern "C" void kernel_launch(void* const* d_in, const int* in_sizes, int n_in,
                              void* d_out, int out_size) {
    const float* x    = (const float*)d_in[0];   // [N, 256] f32
    const void*  edge = d_in[1];                  // [2, E] int32 or int64
    const float* W    = (const float*)d_in[2];   // [256, 128] f32
    const float* a    = (const float*)d_in[3];   // [256] f32
    float* out = (float*)d_out;                   // [E, 1] f32

    const int n = in_sizes[0] / IN_F;   // 100000
    const int e = out_size;             // 3200000

    const int B0 = (n + 255) / 256;
    k_pre<<<B0 + 2, 256>>>(W, a, (const long long*)edge, n, B0);
    k_node_scores<<<(n + 15) / 16, 256>>>(x, n);        // 2 rows per warp
    const int eb = (e / 8 + 255) / 256;
    k_edgeB<<<eb, 256>>>(edge, out, e, n);
    k_recip<<<(n + 255) / 256, 256>>>(n);
    k_edgeC<<<eb, 256>>>(out, e);
}

// round 8
// speedup vs baseline: 1.0788x; 1.0788x over previous
#include <cuda_runtime.h>
#include <math.h>

#define NN 100000
#define EE 3200000
#define IN_F 256
#define ATT_D 128
#define SLOPE 0.2f

// ---------------- device scratch (no runtime allocation allowed) ----------
__device__ float g_wsrc[IN_F];
__device__ float g_wdst[IN_F];
__device__ float g_ssrc[NN];
__device__ float g_sdst[NN];
__device__ float g_denom[NN];
__device__ float g_rden[NN + 4];     // +pad for float4 recip tail
__device__ int   g_srcix[EE];        // int32 src staged by edgeB for edgeC
__device__ int   g_is64;             // 1 if edge buffer is int64, 0 if int32

// ---------------- fused pre-pass -------------------------------------------
// blocks [0,B0): zero denom   | block B0: w = W @ a halves | block B0+1: sniff
__global__ void k_pre(const float* __restrict__ W, const float* __restrict__ a,
                      const long long* __restrict__ edge, int n, int B0) {
    int b = blockIdx.x;
    if (b < B0) {
        int i = b * blockDim.x + threadIdx.x;
        if (i < n) g_denom[i] = 0.0f;
    } else if (b == B0) {
        __shared__ float sa[2 * ATT_D];
        int t = threadIdx.x;            // 256 threads
        sa[t] = a[t];
        __syncthreads();
        const float* row = W + (size_t)t * ATT_D;
        float ws = 0.f, wd = 0.f;
#pragma unroll 8
        for (int j = 0; j < ATT_D; ++j) {
            float w = row[j];
            ws += w * sa[j];
            wd += w * sa[ATT_D + j];
        }
        g_wsrc[t] = ws;
        g_wdst[t] = wd;
    } else {
        // dtype sniff: int32 data read as int64 exits [0,n) with prob ~1
        if (threadIdx.x == 0) {
            int is64 = 1;
            for (int i = 0; i < 256; ++i) {
                long long v = edge[i];
                if (v < 0 || v >= (long long)n) { is64 = 0; break; }
            }
            g_is64 = is64;
        }
    }
}

// ---------------- node scores: one warp per row (R6, near roofline) ---------
__global__ void k_node_scores(const float* __restrict__ x, int n) {
    int gw   = (blockIdx.x * blockDim.x + threadIdx.x) >> 5;
    int lane = threadIdx.x & 31;
    if (gw >= n) return;
    const float4* xr = reinterpret_cast<const float4*>(x + (size_t)gw * IN_F);
    const float4* ws = reinterpret_cast<const float4*>(g_wsrc);
    const float4* wd = reinterpret_cast<const float4*>(g_wdst);
    float a0 = 0.f, a1 = 0.f;
#pragma unroll
    for (int k = 0; k < IN_F / 4 / 32; ++k) {   // 2 iters
        float4 xv = xr[lane + 32 * k];
        float4 sv = __ldg(&ws[lane + 32 * k]);
        float4 dv = __ldg(&wd[lane + 32 * k]);
        a0 += xv.x * sv.x + xv.y * sv.y + xv.z * sv.z + xv.w * sv.w;
        a1 += xv.x * dv.x + xv.y * dv.y + xv.z * dv.z + xv.w * dv.w;
    }
#pragma unroll
    for (int off = 16; off; off >>= 1) {
        a0 += __shfl_xor_sync(0xffffffffu, a0, off);
        a1 += __shfl_xor_sync(0xffffffffu, a1, off);
    }
    if (lane == 0) {
        g_ssrc[gw] = a0;
        g_sdst[gw] = a1;
    }
}

// ---------------- edge pass 1: ex = exp(leaky(score)); segment-sum ----------
// R6's 4-edges/thread form (known-lean), plus int4 srcix staging (L2-resident)
// so edgeC never touches the edge list again. No max subtraction: scores are
// analytically bounded (|s| < ~30 << 88).
__global__ void __launch_bounds__(256) k_edgeB(const void* __restrict__ edge_raw,
                                               float* __restrict__ out,
                                               int e_cnt, int n) {
    int i = (blockIdx.x * blockDim.x + threadIdx.x) << 2;
    if (i >= e_cnt) return;
    const unsigned nm1 = (unsigned)(n - 1);
    int src[4], dst[4];
    bool full = (i + 3 < e_cnt);
    if (g_is64) {
        const long long* ep = (const long long*)edge_raw;
        if (full) {
            longlong2 s0 = *(const longlong2*)(ep + i);
            longlong2 s1 = *(const longlong2*)(ep + i + 2);
            longlong2 d0 = *(const longlong2*)(ep + (size_t)e_cnt + i);
            longlong2 d1 = *(const longlong2*)(ep + (size_t)e_cnt + i + 2);
            src[0] = (int)s0.x; src[1] = (int)s0.y; src[2] = (int)s1.x; src[3] = (int)s1.y;
            dst[0] = (int)d0.x; dst[1] = (int)d0.y; dst[2] = (int)d1.x; dst[3] = (int)d1.y;
        } else {
            for (int k = 0; k < 4; ++k) {
                int e = min(i + k, e_cnt - 1);
                src[k] = (int)ep[e];
                dst[k] = (int)ep[(size_t)e_cnt + e];
            }
        }
    } else {
        const int* ep = (const int*)edge_raw;
        if (full) {
            int4 s = *(const int4*)(ep + i);
            int4 d = *(const int4*)(ep + (size_t)e_cnt + i);
            src[0] = s.x; src[1] = s.y; src[2] = s.z; src[3] = s.w;
            dst[0] = d.x; dst[1] = d.y; dst[2] = d.z; dst[3] = d.w;
        } else {
            for (int k = 0; k < 4; ++k) {
                int e = min(i + k, e_cnt - 1);
                src[k] = ep[e];
                dst[k] = ep[(size_t)e_cnt + e];
            }
        }
    }
    float ex[4];
#pragma unroll
    for (int k = 0; k < 4; ++k) {
        unsigned ss = min((unsigned)src[k], nm1);   // clamp: safety, no-op normally
        unsigned dd = min((unsigned)dst[k], nm1);
        src[k] = (int)ss;
        float s = __ldg(&g_ssrc[ss]) + __ldg(&g_sdst[dd]);
        s = (s >= 0.f) ? s : SLOPE * s;
        ex[k] = __expf(s);
    }
    if (full) {
        *reinterpret_cast<float4*>(out + i) = make_float4(ex[0], ex[1], ex[2], ex[3]);
        *reinterpret_cast<int4*>(g_srcix + i) = make_int4(src[0], src[1], src[2], src[3]);
#pragma unroll
        for (int k = 0; k < 4; ++k) atomicAdd(&g_denom[src[k]], ex[k]);
    } else {
        for (int k = 0; k < 4 && i + k < e_cnt; ++k) {
            out[i + k]     = ex[k];
            g_srcix[i + k] = src[k];
            atomicAdd(&g_denom[src[k]], ex[k]);
        }
    }
}

// ---------------- reciprocal pass: 100k RCPs instead of 3.2M divides --------
__global__ void k_recip(int n) {
    int i = (blockIdx.x * blockDim.x + threadIdx.x) << 2;
    if (i >= n) return;
    float4 d = *reinterpret_cast<const float4*>(g_denom + i);   // n may not be /4: pad handled below
    float4 r;
    r.x = 1.0f / (d.x + 1e-16f);
    r.y = 1.0f / (d.y + 1e-16f);
    r.z = 1.0f / (d.z + 1e-16f);
    r.w = 1.0f / (d.w + 1e-16f);
    *reinterpret_cast<float4*>(g_rden + i) = r;
}

// ---------------- edge pass 2: pure multiply stream -------------------------
__global__ void __launch_bounds__(256) k_edgeC(float* __restrict__ out, int e_cnt) {
    int i = (blockIdx.x * blockDim.x + threadIdx.x) << 2;
    if (i >= e_cnt) return;
    if (i + 3 < e_cnt) {
        int4   s = *reinterpret_cast<const int4*>(g_srcix + i);
        float4 v = *reinterpret_cast<const float4*>(out + i);
        v.x *= __ldg(&g_rden[s.x]);
        v.y *= __ldg(&g_rden[s.y]);
        v.z *= __ldg(&g_rden[s.z]);
        v.w *= __ldg(&g_rden[s.w]);
        *reinterpret_cast<float4*>(out + i) = v;
    } else {
        for (int k = 0; k < 4 && i + k < e_cnt; ++k)
            out[i + k] *= g_rden[g_srcix[i + k]];
    }
}

// ---------------- launch ------------------------------------------------------
extern "C" void kernel_launch(void* const* d_in, const int* in_sizes, int n_in,
                              void* d_out, int out_size) {
    const float* x    = (const float*)d_in[0];   // [N, 256] f32
    const void*  edge = d_in[1];                  // [2, E] int32 or int64
    const float* W    = (const float*)d_in[2];   // [256, 128] f32
    const float* a    = (const float*)d_in[3];   // [256] f32
    float* out = (float*)d_out;                   // [E, 1] f32

    const int n = in_sizes[0] / IN_F;   // 100000
    const int e = out_size;             // 3200000

    const int B0 = (n + 255) / 256;
    k_pre<<<B0 + 2, 256>>>(W, a, (const long long*)edge, n, B0);
    k_node_scores<<<(n + 7) / 8, 256>>>(x, n);          // one warp per row
    const int eb = (e / 4 + 255) / 256;
    k_edgeB<<<eb, 256>>>(edge, out, e, n);
    // n = 100000 is divisible by 4; float4 recip covers it exactly.
    k_recip<<<((n + 3) / 4 + 255) / 256, 256>>>(n);
    k_edgeC<<<eb, 256>>>(out, e);
}